// round 16
// baseline (speedup 1.0000x reference)
#include <cuda_runtime.h>
#include <math.h>

#define NB   32
#define C    256
#define CI   64
#define L    6
#define T    64
#define V    50
#define K    3
#define EPSV 1e-5f

#define XT_ELEMS  (NB*C*L*V)
#define Y_ELEMS   (NB*CI*L*V)
#define OUT_ELEMS (NB*C*T*V)
#define OUT4      (OUT_ELEMS/4)

__device__ __align__(16) float g_xt[XT_ELEMS];
__device__ __align__(16) float g_WdT[C*CI];       // [c][d]
__device__ __align__(16) float g_y[Y_ELEMS];
__device__ __align__(16) float g_epre[NB*L*K*CI]; // [n][l][k][d]
__device__ float g_att[NB*C*L];
__device__ float g_s1[CI], g_q1[CI];
__device__ float g_s2[CI], g_q2[CI];

__constant__ int c_off[7] = {0, 6, 20, 42, 62, 78, 94};
__constant__ int c_layers[94] = {
    1, 0, 20, 26, 25, 45,
    0, 20, 12, 16, 2, 4, 8, 25, 45, 37, 41, 27, 29, 33,
    12, 16, 2, 4, 8, 13, 17, 3, 5, 9, 3, 28, 37, 41, 27, 29, 33, 38, 42, 28, 30, 34,
    13, 17, 3, 5, 9, 14, 18, 6, 10, 3, 28, 38, 42, 28, 30, 34, 39, 43, 31, 35,
    14, 18, 6, 10, 15, 19, 7, 11, 39, 43, 31, 35, 40, 44, 32, 36,
    15, 19, 7, 11, 21, 22, 23, 24, 40, 44, 32, 36, 46, 47, 48, 49
};

// ---------------------------------------------------------------------------
// K1 (half): x_t = max over T (float2) for n in [16*half, 16*half+16).
// Half 0 also transposes W_down + zeroes BN sums.
// Grid 2400 blocks per half.
// ---------------------------------------------------------------------------
__global__ void __launch_bounds__(256) k_maxT(const float* __restrict__ x,
                                              const float* __restrict__ Wd,
                                              int half) {
    if (half == 0) {
        if (blockIdx.x < 64) {
            g_WdT[threadIdx.x * CI + blockIdx.x] = Wd[blockIdx.x * C + threadIdx.x];
        } else if (blockIdx.x == 64 && threadIdx.x < CI) {
            int t = threadIdx.x;
            g_s1[t] = 0.f; g_q1[t] = 0.f; g_s2[t] = 0.f; g_q2[t] = 0.f;
        }
    }
    int i2 = (half * 2400 + blockIdx.x) * 256 + threadIdx.x;   // < XT_ELEMS/2
    int v2  = i2 % (V / 2);
    int ncl = i2 / (V / 2);
    const float2* p = (const float2*)x + (size_t)ncl * (T * V / 2) + v2;
    float ax0 = -INFINITY, ay0 = -INFINITY, ax1 = -INFINITY, ay1 = -INFINITY;
    float ax2 = -INFINITY, ay2 = -INFINITY, ax3 = -INFINITY, ay3 = -INFINITY;
#pragma unroll
    for (int t = 0; t < T; t += 4) {
        float2 q0 = __ldg(p + (t + 0) * (V / 2));
        float2 q1 = __ldg(p + (t + 1) * (V / 2));
        float2 q2 = __ldg(p + (t + 2) * (V / 2));
        float2 q3 = __ldg(p + (t + 3) * (V / 2));
        ax0 = fmaxf(ax0, q0.x); ay0 = fmaxf(ay0, q0.y);
        ax1 = fmaxf(ax1, q1.x); ay1 = fmaxf(ay1, q1.y);
        ax2 = fmaxf(ax2, q2.x); ay2 = fmaxf(ay2, q2.y);
        ax3 = fmaxf(ax3, q3.x); ay3 = fmaxf(ay3, q3.y);
    }
    float2 r;
    r.x = fmaxf(fmaxf(ax0, ax1), fmaxf(ax2, ax3));
    r.y = fmaxf(fmaxf(ay0, ay1), fmaxf(ay2, ay3));
    ((float2*)g_xt)[i2] = r;
}

// ---------------------------------------------------------------------------
// K2 (half): down-proj GEMM + BN1 partials for n in half. Grid 96, 512 thr.
// ---------------------------------------------------------------------------
__global__ void __launch_bounds__(512) k_down(const float* __restrict__ bd,
                                              int half) {
    int p = half * 96 + blockIdx.x;      // 0..191
    int n = p / L;
    int l = p % L;
    __shared__ __align__(16) float sW[128 * 64];
    __shared__ __align__(16) float sx[128 * V];
    int tid = threadIdx.x;
    int v = tid % V;
    int dg = tid / V;
    float acc[8];
#pragma unroll
    for (int i = 0; i < 8; i++) acc[i] = 0.f;

    for (int ch = 0; ch < 2; ch++) {
        int cb = ch * 128;
        const float4* Wg = (const float4*)(g_WdT + cb * CI);
        float4* sW4 = (float4*)sW;
        for (int j = tid; j < 2048; j += 512) sW4[j] = __ldg(Wg + j);
        for (int j = tid; j < 3200; j += 512) {
            int cl = j / 25, v2 = j % 25;
            ((float2*)sx)[cl * 25 + v2] =
                *(const float2*)(g_xt + (size_t)(n * C + cb + cl) * (L * V) + l * V + v2 * 2);
        }
        __syncthreads();
        if (tid < 400) {
#pragma unroll 8
            for (int cl = 0; cl < 128; cl++) {
                float xv = sx[cl * V + v];
                const float4* w4 = (const float4*)(sW + cl * 64 + dg * 8);
                float4 w0 = w4[0], w1 = w4[1];
                acc[0] += w0.x * xv; acc[1] += w0.y * xv; acc[2] += w0.z * xv; acc[3] += w0.w * xv;
                acc[4] += w1.x * xv; acc[5] += w1.y * xv; acc[6] += w1.z * xv; acc[7] += w1.w * xv;
            }
        }
        __syncthreads();
    }
    if (tid < 400) {
#pragma unroll
        for (int i = 0; i < 8; i++) {
            int d = dg * 8 + i;
            float yv = acc[i] + __ldg(&bd[d]);
            g_y[((n * CI + d) * L + l) * V + v] = yv;
            sx[d * V + v] = yv;
        }
    }
    __syncthreads();
    if (tid < CI) {
        float s = 0.f, q = 0.f;
#pragma unroll
        for (int vv = 0; vv < V; vv++) {
            float yv = sx[tid * V + vv];
            s += yv; q += yv * yv;
        }
        atomicAdd(&g_s1[tid], s);
        atomicAdd(&g_q1[tid], q);
    }
}

// ---------------------------------------------------------------------------
// K3: BN1-finalize + xs + topk + edge GEMM + BN2 partials.
// Grid 64 = (n, half-of-l). 384 threads. (Proven R7 form.)
// ---------------------------------------------------------------------------
__global__ void __launch_bounds__(384) k_graph(const float* __restrict__ g1,
                                               const float* __restrict__ b1,
                                               const float* __restrict__ We) {
    int n = blockIdx.x >> 1;
    int half = blockIdx.x & 1;
    int tid = threadIdx.x;
    int d = tid & 63;
    int lf = tid / 64;
    __shared__ float sWe[CI * 129];
    __shared__ float sxs[CI * L];
    __shared__ float sstat[2 * CI];
    __shared__ float sinn[L * L];
    __shared__ int   sidx[L * K];
    __shared__ float sredp[3 * CI], sredq[3 * CI];

    const float4* We4 = (const float4*)We;
    for (int j = tid; j < 2048; j += 384) {
        float4 w = __ldg(We4 + j);
        int dd = j >> 5, c4 = (j & 31) * 4;
        float* p = &sWe[dd * 129 + c4];
        p[0] = w.x; p[1] = w.y; p[2] = w.z; p[3] = w.w;
    }
    if (tid < CI) {
        float s = g_s1[tid], q = g_q1[tid];
        float cnt = (float)(NB * L * V);
        float mean = s / cnt;
        float var  = q / cnt - mean * mean;
        sstat[tid]      = mean;
        sstat[CI + tid] = rsqrtf(var + EPSV);
    }
    __syncthreads();

    {
        float mean = sstat[d], rstd = sstat[CI + d];
        float gm = __ldg(&g1[d]), bt = __ldg(&b1[d]);
        int base = (n * CI + d) * (L * V) + lf * V;
        int o0 = c_off[lf], o1 = c_off[lf + 1];
        float s = 0.f;
        for (int j = o0; j < o1; j++) {
            float yv = (__ldg(&g_y[base + c_layers[j]]) - mean) * rstd * gm + bt;
            s += fmaxf(yv, 0.f);
        }
        sxs[d * L + lf] = s / (float)(o1 - o0);
    }
    __syncthreads();

    if (tid < L * L) {
        int ll = tid / L, mm = tid % L;
        float s = 0.f;
        for (int c = 0; c < CI; c++) s += sxs[c * L + ll] * sxs[c * L + mm];
        sinn[tid] = s;
    }
    __syncthreads();
    if (tid < L) {
        int taken = 0;
        float xl = sinn[tid * L + tid];
        for (int k = 0; k < K; k++) {
            int best = -1; float bv = -INFINITY;
            for (int m = 0; m < L; m++) {
                if ((taken >> m) & 1) continue;
                float pv = 2.f * sinn[tid * L + m] - xl - sinn[m * L + m];
                if (pv > bv) { bv = pv; best = m; }
            }
            taken |= (1 << best);
            sidx[tid * K + k] = best;
        }
    }
    __syncthreads();

    if (tid < 192) {
        int l3 = tid / 64;
        int l = half * 3 + l3;
        int i0 = sidx[l * K + 0], i1 = sidx[l * K + 1], i2 = sidx[l * K + 2];
        float a0 = 0.f, a1 = 0.f, a2 = 0.f;
#pragma unroll 4
        for (int c = 0; c < CI; c++) {
            float wa = sWe[d * 129 + c];
            float wb = sWe[d * 129 + CI + c];
            float ctr = sxs[c * L + l];
            float base = (wb - wa) * ctr;
            a0 += wa * sxs[c * L + i0] + base;
            a1 += wa * sxs[c * L + i1] + base;
            a2 += wa * sxs[c * L + i2] + base;
        }
        int ob = (n * L + l) * K * CI + d;
        g_epre[ob + 0 * CI] = a0;
        g_epre[ob + 1 * CI] = a1;
        g_epre[ob + 2 * CI] = a2;
        sredp[l3 * CI + d] = a0 + a1 + a2;
        sredq[l3 * CI + d] = a0 * a0 + a1 * a1 + a2 * a2;
    }
    __syncthreads();
    if (tid < CI) {
        float s = 0.f, q = 0.f;
#pragma unroll
        for (int l3 = 0; l3 < 3; l3++) {
            s += sredp[l3 * CI + tid];
            q += sredq[l3 * CI + tid];
        }
        atomicAdd(&g_s2[tid], s);
        atomicAdd(&g_q2[tid], q);
    }
}

// ---------------------------------------------------------------------------
// K4 (half): BN2-finalize + e + att for n in half. Grid 96, 256 threads.
// ---------------------------------------------------------------------------
__global__ void __launch_bounds__(256) k_att(const float* __restrict__ g2,
                                             const float* __restrict__ b2,
                                             const float* __restrict__ Wa,
                                             const float* __restrict__ ba,
                                             int half) {
    int tile = half * 96 + blockIdx.x;       // 0..191
    int n = tile / L;
    int l = tile % L;
    int tid = threadIdx.x;
    __shared__ __align__(16) float se[CI];
    if (tid < CI) {
        int d = tid;
        float s = g_s2[d], q = g_q2[d];
        float cnt = (float)(NB * L * K);
        float mean = s / cnt;
        float rstd = rsqrtf(q / cnt - mean * mean + EPSV);
        float gm = __ldg(&g2[d]), bt = __ldg(&b2[d]);
        int base = (n * L + l) * K * CI + d;
        float e0 = __ldg(&g_epre[base + 0 * CI]);
        float e1 = __ldg(&g_epre[base + 1 * CI]);
        float e2 = __ldg(&g_epre[base + 2 * CI]);
        float mx = -INFINITY, ev;
        ev = (e0 - mean) * rstd * gm + bt; ev = (ev >= 0.f) ? ev : 0.2f * ev; mx = fmaxf(mx, ev);
        ev = (e1 - mean) * rstd * gm + bt; ev = (ev >= 0.f) ? ev : 0.2f * ev; mx = fmaxf(mx, ev);
        ev = (e2 - mean) * rstd * gm + bt; ev = (ev >= 0.f) ? ev : 0.2f * ev; mx = fmaxf(mx, ev);
        se[d] = mx;
    }
    __syncthreads();
    float acc = 0.f;
    const float4* Wa4 = (const float4*)(Wa + tid * CI);
    const float4* se4 = (const float4*)se;
#pragma unroll
    for (int j = 0; j < 16; j++) {
        float4 w = __ldg(Wa4 + j);
        float4 e = se4[j];
        acc += w.x * e.x + w.y * e.y + w.z * e.z + w.w * e.w;
    }
    float a = acc + __ldg(&ba[tid]);
    g_att[(n * C + tid) * L + l] = 1.f / (1.f + __expf(-a));
}

// ---------------------------------------------------------------------------
// K5 (half): out = sum_l x*att for n in half. Grid 6400 per half.
// ---------------------------------------------------------------------------
__global__ void __launch_bounds__(256) k_out(const float* __restrict__ x,
                                             float* __restrict__ out,
                                             int half) {
    int base = (half * 6400 + blockIdx.x) * 512 + threadIdx.x;
#pragma unroll
    for (int r = 0; r < 2; r++) {
        int i4 = base + r * 256;
        int tv4 = i4 % (T * V / 4);
        int nc  = i4 / (T * V / 4);
        const float4* px = (const float4*)x + (size_t)nc * (L * T * V / 4) + tv4;
        float a0 = __ldg(&g_att[nc * L + 0]);
        float a1 = __ldg(&g_att[nc * L + 1]);
        float a2 = __ldg(&g_att[nc * L + 2]);
        float a3 = __ldg(&g_att[nc * L + 3]);
        float a4 = __ldg(&g_att[nc * L + 4]);
        float a5 = __ldg(&g_att[nc * L + 5]);
        float4 x0 = __ldg(px + 0 * 800);
        float4 x1 = __ldg(px + 1 * 800);
        float4 x2 = __ldg(px + 2 * 800);
        float4 x3 = __ldg(px + 3 * 800);
        float4 x4 = __ldg(px + 4 * 800);
        float4 x5 = __ldg(px + 5 * 800);
        float4 rr;
        rr.x = a0*x0.x + a1*x1.x + a2*x2.x + a3*x3.x + a4*x4.x + a5*x5.x;
        rr.y = a0*x0.y + a1*x1.y + a2*x2.y + a3*x3.y + a4*x4.y + a5*x5.y;
        rr.z = a0*x0.z + a1*x1.z + a2*x2.z + a3*x3.z + a4*x4.z + a5*x5.z;
        rr.w = a0*x0.w + a1*x1.w + a2*x2.w + a3*x3.w + a4*x4.w + a5*x5.w;
        ((float4*)out)[i4] = rr;
    }
}

// ---------------------------------------------------------------------------
// Launch DAG (fork-join on legacy stream 0):
//   s0: maxT_A ─ evA ─ maxT_B ─ evB ············ wait(evD) out_A  wait(evE) out_B
//   s2:        wait(evA) down_A  wait(evB) down_B  graph  att_A evD  att_B evE
// ---------------------------------------------------------------------------
extern "C" void kernel_launch(void* const* d_in, const int* in_sizes, int n_in,
                              void* d_out, int out_size) {
    const float* x      = (const float*)d_in[0];
    const float* W_down = (const float*)d_in[1];
    const float* b_down = (const float*)d_in[2];
    const float* gamma1 = (const float*)d_in[3];
    const float* beta1  = (const float*)d_in[4];
    const float* W_edge = (const float*)d_in[5];
    const float* gamma2 = (const float*)d_in[6];
    const float* beta2  = (const float*)d_in[7];
    const float* W_agg  = (const float*)d_in[8];
    const float* b_agg  = (const float*)d_in[9];
    float* out = (float*)d_out;

    static cudaStream_t s2 = nullptr;
    static cudaEvent_t evA = nullptr, evB = nullptr, evD = nullptr, evE = nullptr;
    if (s2 == nullptr) {
        cudaStreamCreateWithFlags(&s2, cudaStreamNonBlocking);
        cudaEventCreateWithFlags(&evA, cudaEventDisableTiming);
        cudaEventCreateWithFlags(&evB, cudaEventDisableTiming);
        cudaEventCreateWithFlags(&evD, cudaEventDisableTiming);
        cudaEventCreateWithFlags(&evE, cudaEventDisableTiming);
    }

    k_maxT<<<2400, 256>>>(x, W_down, 0);
    cudaEventRecord(evA, 0);
    k_maxT<<<2400, 256>>>(x, W_down, 1);
    cudaEventRecord(evB, 0);

    cudaStreamWaitEvent(s2, evA, 0);
    k_down<<<96, 512, 0, s2>>>(b_down, 0);           // overlaps maxT_B
    cudaStreamWaitEvent(s2, evB, 0);
    k_down<<<96, 512, 0, s2>>>(b_down, 1);
    k_graph<<<64, 384, 0, s2>>>(gamma1, beta1, W_edge);
    k_att<<<96, 256, 0, s2>>>(gamma2, beta2, W_agg, b_agg, 0);
    cudaEventRecord(evD, s2);
    k_att<<<96, 256, 0, s2>>>(gamma2, beta2, W_agg, b_agg, 1);
    cudaEventRecord(evE, s2);

    cudaStreamWaitEvent(0, evD, 0);
    k_out<<<6400, 256>>>(x, out, 0);                 // overlaps att_B
    cudaStreamWaitEvent(0, evE, 0);
    k_out<<<6400, 256>>>(x, out, 1);
}

// round 17
// speedup vs baseline: 1.1494x; 1.1494x over previous
#include <cuda_runtime.h>
#include <math.h>

#define NB   32
#define C    256
#define CI   64
#define L    6
#define T    64
#define V    50
#define K    3
#define EPSV 1e-5f

#define XT_ELEMS  (NB*C*L*V)
#define Y_ELEMS   (NB*CI*L*V)
#define OUT_ELEMS (NB*C*T*V)

__device__ __align__(16) float g_xt[XT_ELEMS];
__device__ __align__(16) float g_WdT[C*CI];       // [c][d]
__device__ __align__(16) float g_y[Y_ELEMS];
__device__ __align__(16) float g_epre[NB*L*K*CI]; // [n][l][k][d]
__device__ float g_att[NB*C*L];
__device__ float g_s1[CI], g_q1[CI];
__device__ float g_s2[CI], g_q2[CI];
__device__ unsigned int g_c1;                     // graph-role done counter

__constant__ int c_off[7] = {0, 6, 20, 42, 62, 78, 94};
__constant__ int c_layers[94] = {
    1, 0, 20, 26, 25, 45,
    0, 20, 12, 16, 2, 4, 8, 25, 45, 37, 41, 27, 29, 33,
    12, 16, 2, 4, 8, 13, 17, 3, 5, 9, 3, 28, 37, 41, 27, 29, 33, 38, 42, 28, 30, 34,
    13, 17, 3, 5, 9, 14, 18, 6, 10, 3, 28, 38, 42, 28, 30, 34, 39, 43, 31, 35,
    14, 18, 6, 10, 15, 19, 7, 11, 39, 43, 31, 35, 40, 44, 32, 36,
    15, 19, 7, 11, 21, 22, 23, 24, 40, 44, 32, 36, 46, 47, 48, 49
};

// ---------------------------------------------------------------------------
// K1: x_t = max over T (float2). Side: transpose W_down, zero sums + counter.
// ---------------------------------------------------------------------------
__global__ void __launch_bounds__(256) k_maxT(const float* __restrict__ x,
                                              const float* __restrict__ Wd) {
    if (blockIdx.x < 64) {
        g_WdT[threadIdx.x * CI + blockIdx.x] = Wd[blockIdx.x * C + threadIdx.x];
    } else if (blockIdx.x == 64) {
        if (threadIdx.x < CI) {
            int t = threadIdx.x;
            g_s1[t] = 0.f; g_q1[t] = 0.f; g_s2[t] = 0.f; g_q2[t] = 0.f;
        }
        if (threadIdx.x == 64) g_c1 = 0u;
    }
    int i2 = blockIdx.x * 256 + threadIdx.x;
    if (i2 >= XT_ELEMS / 2) return;
    int v2  = i2 % (V / 2);
    int ncl = i2 / (V / 2);
    const float2* p = (const float2*)x + (size_t)ncl * (T * V / 2) + v2;
    float ax0 = -INFINITY, ay0 = -INFINITY, ax1 = -INFINITY, ay1 = -INFINITY;
    float ax2 = -INFINITY, ay2 = -INFINITY, ax3 = -INFINITY, ay3 = -INFINITY;
#pragma unroll
    for (int t = 0; t < T; t += 4) {
        float2 q0 = __ldg(p + (t + 0) * (V / 2));
        float2 q1 = __ldg(p + (t + 1) * (V / 2));
        float2 q2 = __ldg(p + (t + 2) * (V / 2));
        float2 q3 = __ldg(p + (t + 3) * (V / 2));
        ax0 = fmaxf(ax0, q0.x); ay0 = fmaxf(ay0, q0.y);
        ax1 = fmaxf(ax1, q1.x); ay1 = fmaxf(ay1, q1.y);
        ax2 = fmaxf(ax2, q2.x); ay2 = fmaxf(ay2, q2.y);
        ax3 = fmaxf(ax3, q3.x); ay3 = fmaxf(ay3, q3.y);
    }
    float2 r;
    r.x = fmaxf(fmaxf(ax0, ax1), fmaxf(ax2, ax3));
    r.y = fmaxf(fmaxf(ay0, ay1), fmaxf(ay2, ay3));
    ((float2*)g_xt)[i2] = r;
}

// ---------------------------------------------------------------------------
// K2 (PDL): y = W_down @ xt + b, fused BN1 partials. 192 x 512.
// ---------------------------------------------------------------------------
__global__ void __launch_bounds__(512) k_down(const float* __restrict__ bd) {
    cudaGridDependencySynchronize();
    int n = blockIdx.x / L;
    int l = blockIdx.x % L;
    __shared__ __align__(16) float sW[128 * 64];
    __shared__ __align__(16) float sx[128 * V];
    int tid = threadIdx.x;
    int v = tid % V;
    int dg = tid / V;
    float acc[8];
#pragma unroll
    for (int i = 0; i < 8; i++) acc[i] = 0.f;

    for (int ch = 0; ch < 2; ch++) {
        int cb = ch * 128;
        const float4* Wg = (const float4*)(g_WdT + cb * CI);
        float4* sW4 = (float4*)sW;
        for (int j = tid; j < 2048; j += 512) sW4[j] = __ldg(Wg + j);
        for (int j = tid; j < 3200; j += 512) {
            int cl = j / 25, v2 = j % 25;
            ((float2*)sx)[cl * 25 + v2] =
                *(const float2*)(g_xt + (size_t)(n * C + cb + cl) * (L * V) + l * V + v2 * 2);
        }
        __syncthreads();
        if (tid < 400) {
#pragma unroll 8
            for (int cl = 0; cl < 128; cl++) {
                float xv = sx[cl * V + v];
                const float4* w4 = (const float4*)(sW + cl * 64 + dg * 8);
                float4 w0 = w4[0], w1 = w4[1];
                acc[0] += w0.x * xv; acc[1] += w0.y * xv; acc[2] += w0.z * xv; acc[3] += w0.w * xv;
                acc[4] += w1.x * xv; acc[5] += w1.y * xv; acc[6] += w1.z * xv; acc[7] += w1.w * xv;
            }
        }
        __syncthreads();
    }
    if (tid < 400) {
#pragma unroll
        for (int i = 0; i < 8; i++) {
            int d = dg * 8 + i;
            float yv = acc[i] + __ldg(&bd[d]);
            g_y[((n * CI + d) * L + l) * V + v] = yv;
            sx[d * V + v] = yv;
        }
    }
    __syncthreads();
    if (tid < CI) {
        float s = 0.f, q = 0.f;
#pragma unroll
        for (int vv = 0; vv < V; vv++) {
            float yv = sx[tid * V + vv];
            s += yv; q += yv * yv;
        }
        atomicAdd(&g_s1[tid], s);
        atomicAdd(&g_q1[tid], q);
    }
}

// ---------------------------------------------------------------------------
// K3 (PDL, layered): graph role (blocks 0..63) then att role (64..255).
// Att role prefetches Wa into regs, then spins on g_c1 (written by lower-bid
// graph blocks — all wave-1 resident, deadlock-free).
// ---------------------------------------------------------------------------
__global__ void __launch_bounds__(384) k_ga(const float* __restrict__ g1,
                                            const float* __restrict__ b1,
                                            const float* __restrict__ We,
                                            const float* __restrict__ g2,
                                            const float* __restrict__ b2,
                                            const float* __restrict__ Wa,
                                            const float* __restrict__ ba) {
    __shared__ __align__(16) float sm[9300];    // 37 KB role-carved
    __shared__ int sidx[L * K];
    int tid = threadIdx.x;
    int bid = blockIdx.x;

    if (bid < 64) {
        // ==================== graph role ====================
        int n = bid >> 1;
        int half = bid & 1;
        int d = tid & 63;
        int lf = tid / 64;
        float* sWe   = sm;                      // 8256
        float* sxs   = sm + 8256;               // 384
        float* sstat = sm + 8640;               // 128
        float* sinn  = sm + 8768;               // 64
        float* sredp = sm + 8832;               // 192
        float* sredq = sm + 9024;               // 192

        // Stage W_edge (input) before waiting on predecessor data.
        const float4* We4 = (const float4*)We;
        for (int j = tid; j < 2048; j += 384) {
            float4 w = __ldg(We4 + j);
            int dd = j >> 5, c4 = (j & 31) * 4;
            float* p = &sWe[dd * 129 + c4];
            p[0] = w.x; p[1] = w.y; p[2] = w.z; p[3] = w.w;
        }
        float gm_r = __ldg(&g1[d]), bt_r = __ldg(&b1[d]);

        cudaGridDependencySynchronize();        // needs g_s1/g_q1/g_y

        if (tid < CI) {
            float s = g_s1[tid], q = g_q1[tid];
            float cnt = (float)(NB * L * V);
            float mean = s / cnt;
            float var  = q / cnt - mean * mean;
            sstat[tid]      = mean;
            sstat[CI + tid] = rsqrtf(var + EPSV);
        }
        __syncthreads();

        {
            float mean = sstat[d], rstd = sstat[CI + d];
            int base = (n * CI + d) * (L * V) + lf * V;
            int o0 = c_off[lf], o1 = c_off[lf + 1];
            float s = 0.f;
            for (int j = o0; j < o1; j++) {
                float yv = (__ldg(&g_y[base + c_layers[j]]) - mean) * rstd * gm_r + bt_r;
                s += fmaxf(yv, 0.f);
            }
            sxs[d * L + lf] = s / (float)(o1 - o0);
        }
        __syncthreads();

        if (tid < L * L) {
            int ll = tid / L, mm = tid % L;
            float s = 0.f;
            for (int c = 0; c < CI; c++) s += sxs[c * L + ll] * sxs[c * L + mm];
            sinn[tid] = s;
        }
        __syncthreads();
        if (tid < L) {
            int taken = 0;
            float xl = sinn[tid * L + tid];
            for (int k = 0; k < K; k++) {
                int best = -1; float bv = -INFINITY;
                for (int m = 0; m < L; m++) {
                    if ((taken >> m) & 1) continue;
                    float pv = 2.f * sinn[tid * L + m] - xl - sinn[m * L + m];
                    if (pv > bv) { bv = pv; best = m; }
                }
                taken |= (1 << best);
                sidx[tid * K + k] = best;
            }
        }
        __syncthreads();

        if (tid < 192) {
            int l3 = tid / 64;
            int l = half * 3 + l3;
            int i0 = sidx[l * K + 0], i1 = sidx[l * K + 1], i2 = sidx[l * K + 2];
            float a0 = 0.f, a1 = 0.f, a2 = 0.f;
#pragma unroll 4
            for (int c = 0; c < CI; c++) {
                float wa = sWe[d * 129 + c];
                float wb = sWe[d * 129 + CI + c];
                float ctr = sxs[c * L + l];
                float base = (wb - wa) * ctr;
                a0 += wa * sxs[c * L + i0] + base;
                a1 += wa * sxs[c * L + i1] + base;
                a2 += wa * sxs[c * L + i2] + base;
            }
            int ob = (n * L + l) * K * CI + d;
            g_epre[ob + 0 * CI] = a0;
            g_epre[ob + 1 * CI] = a1;
            g_epre[ob + 2 * CI] = a2;
            sredp[l3 * CI + d] = a0 + a1 + a2;
            sredq[l3 * CI + d] = a0 * a0 + a1 * a1 + a2 * a2;
        }
        __syncthreads();
        if (tid < CI) {
            float s = 0.f, q = 0.f;
#pragma unroll
            for (int l3 = 0; l3 < 3; l3++) {
                s += sredp[l3 * CI + tid];
                q += sredq[l3 * CI + tid];
            }
            atomicAdd(&g_s2[tid], s);
            atomicAdd(&g_q2[tid], q);
        }
        __syncthreads();
        if (tid == 0) {
            __threadfence();
            atomicAdd(&g_c1, 1u);
        }
    } else {
        // ==================== att role ====================
        int tile = bid - 64;                    // 0..191
        int tn = tile / L, tl = tile % L;
        float* sse = sm;                        // 64

        // Prefetch (inputs only) BEFORE waiting — overlaps graph phase.
        float4 wreg[16];
        float bb = 0.f, gm = 0.f, bt = 0.f;
        if (tid < 256) {
            const float4* Wa4 = (const float4*)(Wa + tid * CI);
#pragma unroll
            for (int j = 0; j < 16; j++) wreg[j] = __ldg(Wa4 + j);
            bb = __ldg(&ba[tid]);
        }
        if (tid < CI) { gm = __ldg(&g2[tid]); bt = __ldg(&b2[tid]); }

        // Wait for all 64 graph blocks (same kernel, lower bid, resident).
        if (tid == 0) {
            volatile unsigned int* vb = &g_c1;
            while (*vb < 64u) __nanosleep(64);
            __threadfence();
        }
        __syncthreads();

        if (tid < CI) {
            int d = tid;
            float s = g_s2[d], q = g_q2[d];
            float cnt = (float)(NB * L * K);
            float mean = s / cnt;
            float rstd = rsqrtf(q / cnt - mean * mean + EPSV);
            int base = (tn * L + tl) * K * CI + d;
            float e0 = g_epre[base + 0 * CI];
            float e1 = g_epre[base + 1 * CI];
            float e2 = g_epre[base + 2 * CI];
            float mx = -INFINITY, ev;
            ev = (e0 - mean) * rstd * gm + bt; ev = (ev >= 0.f) ? ev : 0.2f * ev; mx = fmaxf(mx, ev);
            ev = (e1 - mean) * rstd * gm + bt; ev = (ev >= 0.f) ? ev : 0.2f * ev; mx = fmaxf(mx, ev);
            ev = (e2 - mean) * rstd * gm + bt; ev = (ev >= 0.f) ? ev : 0.2f * ev; mx = fmaxf(mx, ev);
            sse[d] = mx;
        }
        __syncthreads();
        if (tid < 256) {
            float acc = 0.f;
            const float4* se4 = (const float4*)sse;
#pragma unroll
            for (int j = 0; j < 16; j++) {
                float4 w = wreg[j];
                float4 e = se4[j];
                acc += w.x * e.x + w.y * e.y + w.z * e.z + w.w * e.w;
            }
            float a = acc + bb;
            g_att[(tn * C + tid) * L + tl] = 1.f / (1.f + __expf(-a));
        }
    }
}

// ---------------------------------------------------------------------------
// K4 (PDL): out = sum_l x*att, 2 float4/thread, first-slice x prefetch.
// ---------------------------------------------------------------------------
__global__ void __launch_bounds__(256) k_out(const float* __restrict__ x,
                                             float* __restrict__ out) {
    int base = blockIdx.x * 512 + threadIdx.x;
    const float4* x4b = (const float4*)x;

    int i4a = base;
    int tv4a = i4a % (T * V / 4);
    int nca  = i4a / (T * V / 4);
    const float4* pa = x4b + (size_t)nca * (L * T * V / 4) + tv4a;
    float4 p0 = __ldg(pa + 0 * 800);
    float4 p1 = __ldg(pa + 1 * 800);
    float4 p2 = __ldg(pa + 2 * 800);
    float4 p3 = __ldg(pa + 3 * 800);
    float4 p4 = __ldg(pa + 4 * 800);
    float4 p5 = __ldg(pa + 5 * 800);

    cudaGridDependencySynchronize();

    {
        float a0 = __ldg(&g_att[nca * L + 0]);
        float a1 = __ldg(&g_att[nca * L + 1]);
        float a2 = __ldg(&g_att[nca * L + 2]);
        float a3 = __ldg(&g_att[nca * L + 3]);
        float a4 = __ldg(&g_att[nca * L + 4]);
        float a5 = __ldg(&g_att[nca * L + 5]);
        float4 rr;
        rr.x = a0*p0.x + a1*p1.x + a2*p2.x + a3*p3.x + a4*p4.x + a5*p5.x;
        rr.y = a0*p0.y + a1*p1.y + a2*p2.y + a3*p3.y + a4*p4.y + a5*p5.y;
        rr.z = a0*p0.z + a1*p1.z + a2*p2.z + a3*p3.z + a4*p4.z + a5*p5.z;
        rr.w = a0*p0.w + a1*p1.w + a2*p2.w + a3*p3.w + a4*p4.w + a5*p5.w;
        ((float4*)out)[i4a] = rr;
    }
    {
        int i4 = base + 256;
        if (i4 >= OUT_ELEMS / 4) return;
        int tv4 = i4 % (T * V / 4);
        int nc  = i4 / (T * V / 4);
        const float4* px = x4b + (size_t)nc * (L * T * V / 4) + tv4;
        float a0 = __ldg(&g_att[nc * L + 0]);
        float a1 = __ldg(&g_att[nc * L + 1]);
        float a2 = __ldg(&g_att[nc * L + 2]);
        float a3 = __ldg(&g_att[nc * L + 3]);
        float a4 = __ldg(&g_att[nc * L + 4]);
        float a5 = __ldg(&g_att[nc * L + 5]);
        float4 x0 = __ldg(px + 0 * 800);
        float4 x1 = __ldg(px + 1 * 800);
        float4 x2 = __ldg(px + 2 * 800);
        float4 x3 = __ldg(px + 3 * 800);
        float4 x4 = __ldg(px + 4 * 800);
        float4 x5 = __ldg(px + 5 * 800);
        float4 rr;
        rr.x = a0*x0.x + a1*x1.x + a2*x2.x + a3*x3.x + a4*x4.x + a5*x5.x;
        rr.y = a0*x0.y + a1*x1.y + a2*x2.y + a3*x3.y + a4*x4.y + a5*x5.y;
        rr.z = a0*x0.z + a1*x1.z + a2*x2.z + a3*x3.z + a4*x4.z + a5*x5.z;
        rr.w = a0*x0.w + a1*x1.w + a2*x2.w + a3*x3.w + a4*x4.w + a5*x5.w;
        ((float4*)out)[i4] = rr;
    }
}

// ---------------------------------------------------------------------------
template <typename F, typename... Args>
static void launch_pdl(F func, dim3 grid, dim3 block, Args... args) {
    cudaLaunchConfig_t cfg = {};
    cfg.gridDim = grid;
    cfg.blockDim = block;
    cfg.stream = 0;
    cudaLaunchAttribute attr[1];
    attr[0].id = cudaLaunchAttributeProgrammaticStreamSerialization;
    attr[0].val.programmaticStreamSerializationAllowed = 1;
    cfg.attrs = attr;
    cfg.numAttrs = 1;
    cudaLaunchKernelEx(&cfg, func, args...);
}

extern "C" void kernel_launch(void* const* d_in, const int* in_sizes, int n_in,
                              void* d_out, int out_size) {
    const float* x      = (const float*)d_in[0];
    const float* W_down = (const float*)d_in[1];
    const float* b_down = (const float*)d_in[2];
    const float* gamma1 = (const float*)d_in[3];
    const float* beta1  = (const float*)d_in[4];
    const float* W_edge = (const float*)d_in[5];
    const float* gamma2 = (const float*)d_in[6];
    const float* beta2  = (const float*)d_in[7];
    const float* W_agg  = (const float*)d_in[8];
    const float* b_agg  = (const float*)d_in[9];
    float* out = (float*)d_out;

    k_maxT<<<(XT_ELEMS / 2 + 255) / 256, 256>>>(x, W_down);
    launch_pdl(k_down, dim3(NB * L), dim3(512), b_down);
    launch_pdl(k_ga,   dim3(256),    dim3(384), gamma1, beta1, W_edge,
                                                gamma2, beta2, W_agg, b_agg);
    launch_pdl(k_out,  dim3((OUT_ELEMS / 4 + 511) / 512), dim3(256), x, out);
}